// round 11
// baseline (speedup 1.0000x reference)
#include <cuda_runtime.h>
#include <cstdint>

// FisherLayer: N=8192, D=256, K=32. Single fused persistent kernel.
//   y4[n,k]   = -0.5*( sum_d a*x^2 + u*x + c_k ),  a=w^2, u=2w^2 b, c_k=sum a b^2
//   S0[k], Sx[k,d]=sum_n g*x, Sx2[k,d]=sum_n g*x^2
//   out_mu    = w*(Sx + b*S0)/N
//   out_sigma = (w^2*(Sx2 + 2*b*Sx + b^2*S0) - S0)/(sqrt(2)*N)
// 32-row tiles (3 barriers per 32 rows), params register-resident,
// cp.async tile fill, fused grid barrier + L2-hot reduction.

#define NROWS 8192
#define DD    256
#define KK    32
#define GRID_MAIN 148
#define TROWS 32
#define NTILES (NROWS / TROWS)   // 256
#define THREADS 256

typedef unsigned long long u64;

// g_P[chunk 0..127][row 0..147][32 float4]; col = p*256+d; chunk=col>>5
// float4 = (Sx[2p,d], Sx[2p+1,d], Sx2[2p,d], Sx2[2p+1,d])
__device__ __align__(128) float4 g_P[128 * GRID_MAIN * 32];
__device__ float    g_PS0[GRID_MAIN * KK];
__device__ unsigned g_ctr = 0;   // monotonic across graph replays

__device__ __forceinline__ u64 pack2(float lo, float hi) {
    u64 r; asm("mov.b64 %0, {%1, %2};" : "=l"(r) : "f"(lo), "f"(hi)); return r;
}
__device__ __forceinline__ float2 unpack2(u64 v) {
    float2 f; asm("mov.b64 {%0, %1}, %2;" : "=f"(f.x), "=f"(f.y) : "l"(v)); return f;
}
__device__ __forceinline__ u64 fma2(u64 a, u64 b, u64 c) {
    u64 d; asm("fma.rn.f32x2 %0, %1, %2, %3;" : "=l"(d) : "l"(a), "l"(b), "l"(c)); return d;
}
__device__ __forceinline__ uint32_t smem_u32(const void* p) {
    uint32_t a;
    asm("{ .reg .u64 t; cvta.to.shared.u64 t, %1; cvt.u32.u64 %0, t; }" : "=r"(a) : "l"(p));
    return a;
}
__device__ __forceinline__ void cpa16(uint32_t saddr, const void* g) {
    asm volatile("cp.async.cg.shared.global [%0], [%1], 16;" :: "r"(saddr), "l"(g) : "memory");
}

// dynamic smem (bytes):
//   [0,      65536)  s_x    : 2 x 8192 floats (32 rows x 256), double buffer
//   [65536,  98304)  s_part : 8192 floats [slice 0..7][row 0..31][k 0..31]
//   [98304, 102400)  s_gamma: 1024 floats [row][k]
//   [102400,103424)  s_cred : 256 floats
//   [103424,103432)  s_S0v  : 2 floats
#define SMEM_BYTES 103440

__global__ void __launch_bounds__(THREADS, 1) fisher_all(const float* __restrict__ x,
                                                         const float* __restrict__ w,
                                                         const float* __restrict__ b,
                                                         float* __restrict__ out) {
    extern __shared__ __align__(16) char smem[];
    float* s_xf    = reinterpret_cast<float*>(smem);
    float* s_part  = reinterpret_cast<float*>(smem + 65536);
    float* s_gamma = reinterpret_cast<float*>(smem + 98304);
    float* s_cred  = reinterpret_cast<float*>(smem + 102400);
    float* s_S0v   = reinterpret_cast<float*>(smem + 103424);

    const int tid  = threadIdx.x;
    const int wrp  = tid >> 5;   // 0..7 = phase-A slice
    const int lane = tid & 31;   // phase-A/softmax k
    const int bid  = blockIdx.x;

    const int T = (NTILES - bid + GRID_MAIN - 1) / GRID_MAIN;   // 1 or 2 tiles
    const uint32_t sx_base = smem_u32(s_xf);

    auto fill = [&](int tile, int bi) {
        const char* g = reinterpret_cast<const char*>(x + (size_t)tile * TROWS * DD);
        uint32_t s = sx_base + (uint32_t)bi * 32768u + (uint32_t)tid * 16u;
        #pragma unroll
        for (int i = 0; i < 8; i++)
            cpa16(s + i * 4096u, g + tid * 16 + i * 4096);
        asm volatile("cp.async.commit_group;" ::: "memory");
    };

    fill(bid, 0);   // overlap fill with param build

    // ---- params in regs: warp owns d-slice [wrp*32,+32), lane = k ----
    u64 ap[16], up[16];
    float c_part = 0.0f;
    {
        const float* wr = w + lane * DD + wrp * 32;
        const float* br = b + lane * DD + wrp * 32;
        #pragma unroll
        for (int j = 0; j < 16; j++) {
            float w0 = wr[2 * j], w1 = wr[2 * j + 1];
            float b0 = br[2 * j], b1 = br[2 * j + 1];
            float a0 = w0 * w0, a1 = w1 * w1;
            ap[j] = pack2(a0, a1);
            up[j] = pack2(2.0f * a0 * b0, 2.0f * a1 * b1);
            c_part += a0 * b0 * b0 + a1 * b1 * b1;
        }
    }
    s_cred[wrp * KK + lane] = c_part;
    __syncthreads();
    float c_reg = 0.0f;
    #pragma unroll
    for (int j = 0; j < 8; j++) c_reg += s_cred[j * KK + lane];

    // phase-B accumulators: thread owns d = tid, all 32 k as 16 pairs
    u64 accx[16], accx2[16];
    #pragma unroll
    for (int p = 0; p < 16; p++) { accx[p] = 0ull; accx2[p] = 0ull; }
    float s0acc = 0.0f;

    for (int t = 0; t < T; t++) {
        asm volatile("cp.async.wait_group 0;" ::: "memory");
        __syncthreads();   // tile t ready in buffer (t&1)

        const float*      xb = s_xf + (t & 1) * 8192;
        const ulonglong2* bx = reinterpret_cast<const ulonglong2*>(xb);

        // ---- phase A: 4 octets x 8 rows, warp slice = 32 d ----
        #pragma unroll
        for (int oct = 0; oct < 4; oct++) {
            u64 accA[8];
            #pragma unroll
            for (int r = 0; r < 8; r++) accA[r] = 0ull;
            #pragma unroll
            for (int q = 0; q < 8; q++) {
                #pragma unroll
                for (int r = 0; r < 8; r++) {
                    ulonglong2 v = bx[(oct * 8 + r) * 64 + wrp * 8 + q];
                    accA[r] = fma2(v.x, fma2(ap[2 * q],     v.x, up[2 * q]),     accA[r]);
                    accA[r] = fma2(v.y, fma2(ap[2 * q + 1], v.y, up[2 * q + 1]), accA[r]);
                }
            }
            #pragma unroll
            for (int r = 0; r < 8; r++) {
                float2 p = unpack2(accA[r]);
                s_part[wrp * 1024 + (oct * 8 + r) * 32 + lane] = p.x + p.y;
            }
        }
        __syncthreads();

        // ---- softmax: warp handles rows wrp, wrp+8, wrp+16, wrp+24 ----
        #pragma unroll
        for (int i = 0; i < 4; i++) {
            int row = wrp + i * 8;
            float y = 0.0f;
            #pragma unroll
            for (int j = 0; j < 8; j++) y += s_part[j * 1024 + row * 32 + lane];
            y = -0.5f * (y + c_reg);
            float m = y;
            #pragma unroll
            for (int o = 16; o; o >>= 1) m = fmaxf(m, __shfl_xor_sync(0xffffffffu, m, o));
            float e = __expf(y - m);
            float s = e;
            #pragma unroll
            for (int o = 16; o; o >>= 1) s += __shfl_xor_sync(0xffffffffu, s, o);
            float g = e / s;
            s0acc += g;
            s_gamma[row * 32 + lane] = g;
        }
        __syncthreads();

        // prefetch next tile into the other buffer (overlaps phase B)
        if (t + 1 < T) fill(bid + GRID_MAIN, (t + 1) & 1);

        // ---- phase B: 32 rows, thread owns d = tid, 16 k-pairs ----
        #pragma unroll 4
        for (int row = 0; row < TROWS; row++) {
            float xv = xb[row * 256 + tid];
            u64 px = pack2(xv, xv);
            float sq = xv * xv;
            u64 px2 = pack2(sq, sq);
            const ulonglong2* grow =
                reinterpret_cast<const ulonglong2*>(s_gamma + row * 32);
            #pragma unroll
            for (int q = 0; q < 8; q++) {
                ulonglong2 gg = grow[q];
                accx [2 * q]     = fma2(gg.x, px,  accx [2 * q]);
                accx2[2 * q]     = fma2(gg.x, px2, accx2[2 * q]);
                accx [2 * q + 1] = fma2(gg.y, px,  accx [2 * q + 1]);
                accx2[2 * q + 1] = fma2(gg.y, px2, accx2[2 * q + 1]);
            }
        }
        __syncthreads();   // protect s_gamma/s_part before next tile's phase A
    }

    // ---- S0 per-block combine ----
    s_cred[wrp * KK + lane] = s0acc;
    __syncthreads();
    if (wrp == 0) {
        float v = 0.0f;
        #pragma unroll
        for (int j = 0; j < 8; j++) v += s_cred[j * KK + lane];
        g_PS0[bid * KK + lane] = v;
    }

    // ---- write partials: chunk-major, coalesced ----
    {
        ulonglong2* pg = reinterpret_cast<ulonglong2*>(g_P);
        #pragma unroll
        for (int p = 0; p < 16; p++) {
            int chunk = p * 8 + (tid >> 5);
            size_t idx = ((size_t)chunk * GRID_MAIN + bid) * 32 + (tid & 31);
            ulonglong2 v; v.x = accx[p]; v.y = accx2[p];
            pg[idx] = v;
        }
    }

    // ---- grid-wide barrier (148 CTAs, 1/SM) ----
    __threadfence();
    __syncthreads();
    if (bid >= 128) {
        if (tid == 0) atomicAdd(&g_ctr, 1u);
        return;
    }
    if (tid == 0) {
        unsigned my = atomicAdd(&g_ctr, 1u);
        unsigned target = my - (my % (unsigned)GRID_MAIN) + (unsigned)GRID_MAIN;
        while (*(volatile unsigned*)&g_ctr < target) { }
    }
    __syncthreads();
    __threadfence();

    // ---- fused reduction + finalize: blocks 0..127, one chunk each ----
    const int cb = bid;
    const float4* src = g_P + (size_t)cb * GRID_MAIN * 32;
    float4* s_red4 = reinterpret_cast<float4*>(s_part);
    const int q4 = tid & 31;
    const int rg = tid >> 5;
    float4 a = make_float4(0.f, 0.f, 0.f, 0.f);
    #pragma unroll 2
    for (int r = rg; r < GRID_MAIN; r += 8) {
        float4 v = src[r * 32 + q4];
        a.x += v.x; a.y += v.y; a.z += v.z; a.w += v.w;
    }
    s_red4[rg * 32 + q4] = a;

    if (wrp == 1) {   // S0 for this chunk's two k's
        int ks = lane >> 4;
        int j  = lane & 15;
        int p  = cb >> 3;
        float s = 0.0f;
        for (int bb = j; bb < GRID_MAIN; bb += 16) s += g_PS0[bb * KK + 2 * p + ks];
        #pragma unroll
        for (int o = 1; o < 16; o <<= 1) s += __shfl_xor_sync(0xffffffffu, s, o);
        if (j == 0) s_S0v[ks] = s;
    }
    __syncthreads();

    if (tid < 32) {
        float4 tot = make_float4(0.f, 0.f, 0.f, 0.f);
        #pragma unroll
        for (int gq = 0; gq < 8; gq++) {
            float4 v = s_red4[gq * 32 + tid];
            tot.x += v.x; tot.y += v.y; tot.z += v.z; tot.w += v.w;
        }
        const int p  = cb >> 3;
        const int d  = (cb & 7) * 32 + tid;
        const int k0 = 2 * p, k1 = 2 * p + 1;
        const float invN   = 1.0f / (float)NROWS;
        const float invNs2 = invN * 0.70710678118654752440f;

        {
            float wv = w[k0 * DD + d], bv = b[k0 * DD + d], S0 = s_S0v[0];
            float mu  = wv * (tot.x + bv * S0) * invN;
            float Ey2 = wv * wv * (tot.z + 2.0f * bv * tot.x + bv * bv * S0);
            out[k0 * DD + d]           = (Ey2 - S0) * invNs2;
            out[KK * DD + k0 * DD + d] = mu;
        }
        {
            float wv = w[k1 * DD + d], bv = b[k1 * DD + d], S0 = s_S0v[1];
            float mu  = wv * (tot.y + bv * S0) * invN;
            float Ey2 = wv * wv * (tot.w + 2.0f * bv * tot.y + bv * bv * S0);
            out[k1 * DD + d]           = (Ey2 - S0) * invNs2;
            out[KK * DD + k1 * DD + d] = mu;
        }
    }
}

extern "C" void kernel_launch(void* const* d_in, const int* in_sizes, int n_in,
                              void* d_out, int out_size) {
    const float* x = (const float*)d_in[0];
    const float* w = (const float*)d_in[1];
    const float* b = (const float*)d_in[2];
    float* out = (float*)d_out;
    (void)in_sizes; (void)n_in; (void)out_size;

    cudaFuncSetAttribute(fisher_all, cudaFuncAttributeMaxDynamicSharedMemorySize,
                         SMEM_BYTES);
    fisher_all<<<GRID_MAIN, THREADS, SMEM_BYTES>>>(x, w, b, out);
}

// round 12
// speedup vs baseline: 1.0600x; 1.0600x over previous
#include <cuda_runtime.h>
#include <cstdint>

// FisherLayer: N=8192, D=256, K=32 — two-pass streaming decomposition.
//   K1: gamma[n,k] = softmax_k(-0.5*(sum_d a*x^2 + u*x + c_k)), a=w^2, u=2w^2b
//   K2: Sx[k,d] = sum_n g*x, Sx2[k,d] = sum_n g*x^2  (per-block partials)
//   K3: reduce partials + S0; out_mu = w*(Sx+b*S0)/N;
//       out_sigma = (w^2*(Sx2+2b*Sx+b^2*S0) - S0)/(sqrt(2)N)

#define NROWS 8192
#define DD    256
#define KK    32
#define CTAS  128          // K1/K2/K3 grids
#define RPC   64           // rows per CTA (K1, K2)
#define CHUNK 16           // K1 chunk rows

typedef unsigned long long u64;

__device__ float g_G[NROWS * KK];                       // gamma, 1MB
__device__ __align__(128) float4 g_P[128 * CTAS * 32];  // partials, 8.4MB
__device__ float g_PS0[CTAS * KK];

__device__ __forceinline__ u64 pack2(float lo, float hi) {
    u64 r; asm("mov.b64 %0, {%1, %2};" : "=l"(r) : "f"(lo), "f"(hi)); return r;
}
__device__ __forceinline__ float2 unpack2(u64 v) {
    float2 f; asm("mov.b64 {%0, %1}, %2;" : "=f"(f.x), "=f"(f.y) : "l"(v)); return f;
}
__device__ __forceinline__ u64 fma2(u64 a, u64 b, u64 c) {
    u64 d; asm("fma.rn.f32x2 %0, %1, %2, %3;" : "=l"(d) : "l"(a), "l"(b), "l"(c)); return d;
}
__device__ __forceinline__ uint32_t smem_u32(const void* p) {
    uint32_t a;
    asm("{ .reg .u64 t; cvta.to.shared.u64 t, %1; cvt.u32.u64 %0, t; }" : "=r"(a) : "l"(p));
    return a;
}
__device__ __forceinline__ void cpa16(uint32_t saddr, const void* g) {
    asm volatile("cp.async.cg.shared.global [%0], [%1], 16;" :: "r"(saddr), "l"(g) : "memory");
}

// ================= K1: gamma =================
// dyn smem: [0,32768) x double buf (2 x 16 rows x 256 f32)
//           [32768,49152) s_part [slice 8][row 16][k 32]
//           [49152,50176) s_cred
#define SMEM1 50176

__global__ void __launch_bounds__(256, 1) k1_gamma(const float* __restrict__ x,
                                                   const float* __restrict__ w,
                                                   const float* __restrict__ b) {
    extern __shared__ __align__(16) char smem[];
    float* s_x    = reinterpret_cast<float*>(smem);
    float* s_part = reinterpret_cast<float*>(smem + 32768);
    float* s_cred = reinterpret_cast<float*>(smem + 49152);

    const int tid  = threadIdx.x;
    const int wrp  = tid >> 5;
    const int lane = tid & 31;
    const int bid  = blockIdx.x;
    const uint32_t sxb = smem_u32(s_x);

    auto fill = [&](int c) {
        const char* g = reinterpret_cast<const char*>(
            x + (size_t)(bid * RPC + c * CHUNK) * DD);
        uint32_t s = sxb + (uint32_t)(c & 1) * 16384u + (uint32_t)tid * 16u;
        #pragma unroll
        for (int i = 0; i < 4; i++) cpa16(s + i * 4096u, g + tid * 16 + i * 4096);
        asm volatile("cp.async.commit_group;" ::: "memory");
    };

    fill(0);

    // params: warp owns d-slice [wrp*32,+32), lane = k
    u64 ap[16], up[16];
    float c_part = 0.0f;
    {
        const float* wr = w + lane * DD + wrp * 32;
        const float* br = b + lane * DD + wrp * 32;
        #pragma unroll
        for (int j = 0; j < 16; j++) {
            float w0 = wr[2 * j], w1 = wr[2 * j + 1];
            float b0 = br[2 * j], b1 = br[2 * j + 1];
            float a0 = w0 * w0, a1 = w1 * w1;
            ap[j] = pack2(a0, a1);
            up[j] = pack2(2.0f * a0 * b0, 2.0f * a1 * b1);
            c_part += a0 * b0 * b0 + a1 * b1 * b1;
        }
    }
    s_cred[wrp * KK + lane] = c_part;
    __syncthreads();
    float c_reg = 0.0f;
    #pragma unroll
    for (int j = 0; j < 8; j++) c_reg += s_cred[j * KK + lane];

    float s0acc = 0.0f;

    #pragma unroll 1
    for (int c = 0; c < RPC / CHUNK; c++) {
        if (c + 1 < RPC / CHUNK) fill(c + 1);
        if (c + 1 < RPC / CHUNK) {
            asm volatile("cp.async.wait_group 1;" ::: "memory");
        } else {
            asm volatile("cp.async.wait_group 0;" ::: "memory");
        }
        __syncthreads();

        const ulonglong2* bx =
            reinterpret_cast<const ulonglong2*>(s_x + (c & 1) * 4096);

        u64 accA[16];
        #pragma unroll
        for (int r = 0; r < 16; r++) accA[r] = 0ull;
        #pragma unroll
        for (int q = 0; q < 8; q++) {
            #pragma unroll
            for (int r = 0; r < 16; r++) {
                ulonglong2 v = bx[r * 64 + wrp * 8 + q];
                accA[r] = fma2(v.x, fma2(ap[2 * q],     v.x, up[2 * q]),     accA[r]);
                accA[r] = fma2(v.y, fma2(ap[2 * q + 1], v.y, up[2 * q + 1]), accA[r]);
            }
        }
        #pragma unroll
        for (int r = 0; r < 16; r++) {
            float2 p = unpack2(accA[r]);
            s_part[wrp * 512 + r * 32 + lane] = p.x + p.y;
        }
        __syncthreads();

        // softmax: warp handles rows wrp and wrp+8 of this chunk
        #pragma unroll
        for (int i = 0; i < 2; i++) {
            int row = wrp + i * 8;
            float y = 0.0f;
            #pragma unroll
            for (int j = 0; j < 8; j++) y += s_part[j * 512 + row * 32 + lane];
            y = -0.5f * (y + c_reg);
            float m = y;
            #pragma unroll
            for (int o = 16; o; o >>= 1) m = fmaxf(m, __shfl_xor_sync(0xffffffffu, m, o));
            float e = __expf(y - m);
            float s = e;
            #pragma unroll
            for (int o = 16; o; o >>= 1) s += __shfl_xor_sync(0xffffffffu, s, o);
            float g = e / s;
            s0acc += g;
            g_G[(size_t)(bid * RPC + c * CHUNK + row) * KK + lane] = g;
        }
        __syncthreads();   // s_part reuse
    }

    s_cred[wrp * KK + lane] = s0acc;
    __syncthreads();
    if (wrp == 0) {
        float v = 0.0f;
        #pragma unroll
        for (int j = 0; j < 8; j++) v += s_cred[j * KK + lane];
        g_PS0[bid * KK + lane] = v;
    }
}

// ================= K2: weighted accumulation =================
__global__ void __launch_bounds__(256, 1) k2_accum(const float* __restrict__ x) {
    __shared__ __align__(16) float s_g[RPC * KK];   // 8KB

    const int tid = threadIdx.x;
    const int bid = blockIdx.x;
    const int base_row = bid * RPC;

    {   // stage gamma for 64 rows, coalesced
        const float4* gg = reinterpret_cast<const float4*>(g_G + (size_t)base_row * KK);
        float4* sg4 = reinterpret_cast<float4*>(s_g);
        sg4[tid] = gg[tid];
        sg4[tid + 256] = gg[tid + 256];
    }
    __syncthreads();

    u64 accx[16], accx2[16];
    #pragma unroll
    for (int p = 0; p < 16; p++) { accx[p] = 0ull; accx2[p] = 0ull; }

    const float* xb = x + (size_t)base_row * DD + tid;

    #pragma unroll 1
    for (int r0 = 0; r0 < RPC; r0 += 4) {
        float xv[4];
        #pragma unroll
        for (int i = 0; i < 4; i++) xv[i] = xb[(r0 + i) * DD];

        #pragma unroll
        for (int i = 0; i < 4; i++) {
            float v = xv[i];
            u64 px = pack2(v, v);
            float sq = v * v;
            u64 px2 = pack2(sq, sq);
            const ulonglong2* grow =
                reinterpret_cast<const ulonglong2*>(s_g + (r0 + i) * KK);
            #pragma unroll
            for (int q = 0; q < 8; q++) {
                ulonglong2 gg = grow[q];
                accx [2 * q]     = fma2(gg.x, px,  accx [2 * q]);
                accx2[2 * q]     = fma2(gg.x, px2, accx2[2 * q]);
                accx [2 * q + 1] = fma2(gg.y, px,  accx [2 * q + 1]);
                accx2[2 * q + 1] = fma2(gg.y, px2, accx2[2 * q + 1]);
            }
        }
    }

    // partials: chunk-major, coalesced STG.128
    ulonglong2* pg = reinterpret_cast<ulonglong2*>(g_P);
    #pragma unroll
    for (int p = 0; p < 16; p++) {
        int chunk = p * 8 + (tid >> 5);
        size_t idx = ((size_t)chunk * CTAS + bid) * 32 + (tid & 31);
        ulonglong2 v; v.x = accx[p]; v.y = accx2[p];
        pg[idx] = v;
    }
}

// ================= K3: reduce + finalize =================
__global__ void __launch_bounds__(256) k3_fin(const float* __restrict__ w,
                                              const float* __restrict__ b,
                                              float* __restrict__ out) {
    __shared__ __align__(16) float4 s_red4[8 * 32];
    __shared__ float s_S0v[2];

    const int tid  = threadIdx.x;
    const int wrp  = tid >> 5;
    const int lane = tid & 31;
    const int cb   = blockIdx.x;

    const float4* src = g_P + (size_t)cb * CTAS * 32;
    const int q4 = tid & 31;
    const int rg = tid >> 5;   // 8 row-groups over 128 source blocks
    float4 a = make_float4(0.f, 0.f, 0.f, 0.f);
    #pragma unroll
    for (int r = rg; r < CTAS; r += 8) {
        float4 v = src[r * 32 + q4];
        a.x += v.x; a.y += v.y; a.z += v.z; a.w += v.w;
    }
    s_red4[rg * 32 + q4] = a;

    if (wrp == 1) {   // S0 for this chunk's two k's
        int ks = lane >> 4;
        int j  = lane & 15;
        int p  = cb >> 3;
        float s = 0.0f;
        #pragma unroll
        for (int bb = j; bb < CTAS; bb += 16) s += g_PS0[bb * KK + 2 * p + ks];
        #pragma unroll
        for (int o = 1; o < 16; o <<= 1) s += __shfl_xor_sync(0xffffffffu, s, o);
        if (j == 0) s_S0v[ks] = s;
    }
    __syncthreads();

    if (tid < 32) {
        float4 tot = make_float4(0.f, 0.f, 0.f, 0.f);
        #pragma unroll
        for (int gq = 0; gq < 8; gq++) {
            float4 v = s_red4[gq * 32 + tid];
            tot.x += v.x; tot.y += v.y; tot.z += v.z; tot.w += v.w;
        }
        const int p  = cb >> 3;
        const int d  = (cb & 7) * 32 + tid;
        const int k0 = 2 * p, k1 = 2 * p + 1;
        const float invN   = 1.0f / (float)NROWS;
        const float invNs2 = invN * 0.70710678118654752440f;

        {
            float wv = w[k0 * DD + d], bv = b[k0 * DD + d], S0 = s_S0v[0];
            float mu  = wv * (tot.x + bv * S0) * invN;
            float Ey2 = wv * wv * (tot.z + 2.0f * bv * tot.x + bv * bv * S0);
            out[k0 * DD + d]           = (Ey2 - S0) * invNs2;
            out[KK * DD + k0 * DD + d] = mu;
        }
        {
            float wv = w[k1 * DD + d], bv = b[k1 * DD + d], S0 = s_S0v[1];
            float mu  = wv * (tot.y + bv * S0) * invN;
            float Ey2 = wv * wv * (tot.w + 2.0f * bv * tot.y + bv * bv * S0);
            out[k1 * DD + d]           = (Ey2 - S0) * invNs2;
            out[KK * DD + k1 * DD + d] = mu;
        }
    }
}

extern "C" void kernel_launch(void* const* d_in, const int* in_sizes, int n_in,
                              void* d_out, int out_size) {
    const float* x = (const float*)d_in[0];
    const float* w = (const float*)d_in[1];
    const float* b = (const float*)d_in[2];
    float* out = (float*)d_out;
    (void)in_sizes; (void)n_in; (void)out_size;

    cudaFuncSetAttribute(k1_gamma, cudaFuncAttributeMaxDynamicSharedMemorySize, SMEM1);
    k1_gamma<<<CTAS, 256, SMEM1>>>(x, w, b);
    k2_accum<<<CTAS, 256>>>(x);
    k3_fin<<<CTAS, 256>>>(w, b, out);
}

// round 13
// speedup vs baseline: 1.0720x; 1.0113x over previous
#include <cuda_runtime.h>
#include <cstdint>

// FisherLayer: N=8192, D=256, K=32 — two-pass streaming decomposition.
//   K1: gamma[n,k] = softmax_k(-0.5*(sum_d a*x^2 + u*x + c_k)), a=w^2, u=2w^2b
//   K2: Sx[k,d] = sum_n g*x, Sx2[k,d] = sum_n g*x^2  (per-block partials)
//   K3: reduce partials + S0; out_mu = w*(Sx+b*S0)/N;
//       out_sigma = (w^2*(Sx2+2b*Sx+b^2*S0) - S0)/(sqrt(2)N)

#define NROWS 8192
#define DD    256
#define KK    32
#define CTAS  128          // K1/K2/K3 grids
#define RPC   64           // rows per CTA (K1, K2)
#define CHUNK 16           // K1 chunk rows

typedef unsigned long long u64;

__device__ float g_G[NROWS * KK];                       // gamma, 1MB
__device__ __align__(128) float4 g_P[128 * CTAS * 32];  // partials, 8.4MB
__device__ float g_PS0[CTAS * KK];

__device__ __forceinline__ u64 pack2(float lo, float hi) {
    u64 r; asm("mov.b64 %0, {%1, %2};" : "=l"(r) : "f"(lo), "f"(hi)); return r;
}
__device__ __forceinline__ float2 unpack2(u64 v) {
    float2 f; asm("mov.b64 {%0, %1}, %2;" : "=f"(f.x), "=f"(f.y) : "l"(v)); return f;
}
__device__ __forceinline__ u64 fma2(u64 a, u64 b, u64 c) {
    u64 d; asm("fma.rn.f32x2 %0, %1, %2, %3;" : "=l"(d) : "l"(a), "l"(b), "l"(c)); return d;
}
__device__ __forceinline__ uint32_t smem_u32(const void* p) {
    uint32_t a;
    asm("{ .reg .u64 t; cvta.to.shared.u64 t, %1; cvt.u32.u64 %0, t; }" : "=r"(a) : "l"(p));
    return a;
}
__device__ __forceinline__ void cpa16(uint32_t saddr, const void* g) {
    asm volatile("cp.async.cg.shared.global [%0], [%1], 16;" :: "r"(saddr), "l"(g) : "memory");
}

// ================= K1: gamma =================
// dyn smem: [0,32768) x double buf (2 x 16 rows x 256 f32)
//           [32768,49152) s_part [slice 8][row 16][k 32]
//           [49152,50176) s_cred
#define SMEM1 50176

__global__ void __launch_bounds__(256, 1) k1_gamma(const float* __restrict__ x,
                                                   const float* __restrict__ w,
                                                   const float* __restrict__ b) {
    extern __shared__ __align__(16) char smem[];
    float* s_x    = reinterpret_cast<float*>(smem);
    float* s_part = reinterpret_cast<float*>(smem + 32768);
    float* s_cred = reinterpret_cast<float*>(smem + 49152);

    const int tid  = threadIdx.x;
    const int wrp  = tid >> 5;
    const int lane = tid & 31;
    const int bid  = blockIdx.x;
    const uint32_t sxb = smem_u32(s_x);

    auto fill = [&](int c) {
        const char* g = reinterpret_cast<const char*>(
            x + (size_t)(bid * RPC + c * CHUNK) * DD);
        uint32_t s = sxb + (uint32_t)(c & 1) * 16384u + (uint32_t)tid * 16u;
        #pragma unroll
        for (int i = 0; i < 4; i++) cpa16(s + i * 4096u, g + tid * 16 + i * 4096);
        asm volatile("cp.async.commit_group;" ::: "memory");
    };

    fill(0);

    // params: warp owns d-slice [wrp*32,+32), lane = k
    u64 ap[16], up[16];
    float c_part = 0.0f;
    {
        const float* wr = w + lane * DD + wrp * 32;
        const float* br = b + lane * DD + wrp * 32;
        #pragma unroll
        for (int j = 0; j < 16; j++) {
            float w0 = wr[2 * j], w1 = wr[2 * j + 1];
            float b0 = br[2 * j], b1 = br[2 * j + 1];
            float a0 = w0 * w0, a1 = w1 * w1;
            ap[j] = pack2(a0, a1);
            up[j] = pack2(2.0f * a0 * b0, 2.0f * a1 * b1);
            c_part += a0 * b0 * b0 + a1 * b1 * b1;
        }
    }
    s_cred[wrp * KK + lane] = c_part;
    __syncthreads();
    float c_reg = 0.0f;
    #pragma unroll
    for (int j = 0; j < 8; j++) c_reg += s_cred[j * KK + lane];

    float s0acc = 0.0f;

    #pragma unroll 1
    for (int c = 0; c < RPC / CHUNK; c++) {
        if (c + 1 < RPC / CHUNK) fill(c + 1);
        if (c + 1 < RPC / CHUNK) {
            asm volatile("cp.async.wait_group 1;" ::: "memory");
        } else {
            asm volatile("cp.async.wait_group 0;" ::: "memory");
        }
        __syncthreads();

        const ulonglong2* bx =
            reinterpret_cast<const ulonglong2*>(s_x + (c & 1) * 4096);

        u64 accA[16];
        #pragma unroll
        for (int r = 0; r < 16; r++) accA[r] = 0ull;
        #pragma unroll
        for (int q = 0; q < 8; q++) {
            #pragma unroll
            for (int r = 0; r < 16; r++) {
                ulonglong2 v = bx[r * 64 + wrp * 8 + q];
                accA[r] = fma2(v.x, fma2(ap[2 * q],     v.x, up[2 * q]),     accA[r]);
                accA[r] = fma2(v.y, fma2(ap[2 * q + 1], v.y, up[2 * q + 1]), accA[r]);
            }
        }
        #pragma unroll
        for (int r = 0; r < 16; r++) {
            float2 p = unpack2(accA[r]);
            s_part[wrp * 512 + r * 32 + lane] = p.x + p.y;
        }
        __syncthreads();

        // softmax: warp handles rows wrp and wrp+8 of this chunk
        #pragma unroll
        for (int i = 0; i < 2; i++) {
            int row = wrp + i * 8;
            float y = 0.0f;
            #pragma unroll
            for (int j = 0; j < 8; j++) y += s_part[j * 512 + row * 32 + lane];
            y = -0.5f * (y + c_reg);
            float m = y;
            #pragma unroll
            for (int o = 16; o; o >>= 1) m = fmaxf(m, __shfl_xor_sync(0xffffffffu, m, o));
            float e = __expf(y - m);
            float s = e;
            #pragma unroll
            for (int o = 16; o; o >>= 1) s += __shfl_xor_sync(0xffffffffu, s, o);
            float g = e / s;
            s0acc += g;
            g_G[(size_t)(bid * RPC + c * CHUNK + row) * KK + lane] = g;
        }
        __syncthreads();   // s_part reuse
    }

    s_cred[wrp * KK + lane] = s0acc;
    __syncthreads();
    if (wrp == 0) {
        float v = 0.0f;
        #pragma unroll
        for (int j = 0; j < 8; j++) v += s_cred[j * KK + lane];
        g_PS0[bid * KK + lane] = v;
    }
}

// ================= K2: weighted accumulation =================
__global__ void __launch_bounds__(256, 1) k2_accum(const float* __restrict__ x) {
    __shared__ __align__(16) float s_g[RPC * KK];   // 8KB

    const int tid = threadIdx.x;
    const int bid = blockIdx.x;
    const int base_row = bid * RPC;

    {   // stage gamma for 64 rows, coalesced
        const float4* gg = reinterpret_cast<const float4*>(g_G + (size_t)base_row * KK);
        float4* sg4 = reinterpret_cast<float4*>(s_g);
        sg4[tid] = gg[tid];
        sg4[tid + 256] = gg[tid + 256];
    }
    __syncthreads();

    u64 accx[16], accx2[16];
    #pragma unroll
    for (int p = 0; p < 16; p++) { accx[p] = 0ull; accx2[p] = 0ull; }

    const float* xb = x + (size_t)base_row * DD + tid;

    #pragma unroll 1
    for (int r0 = 0; r0 < RPC; r0 += 4) {
        float xv[4];
        #pragma unroll
        for (int i = 0; i < 4; i++) xv[i] = xb[(r0 + i) * DD];

        #pragma unroll
        for (int i = 0; i < 4; i++) {
            float v = xv[i];
            u64 px = pack2(v, v);
            float sq = v * v;
            u64 px2 = pack2(sq, sq);
            const ulonglong2* grow =
                reinterpret_cast<const ulonglong2*>(s_g + (r0 + i) * KK);
            #pragma unroll
            for (int q = 0; q < 8; q++) {
                ulonglong2 gg = grow[q];
                accx [2 * q]     = fma2(gg.x, px,  accx [2 * q]);
                accx2[2 * q]     = fma2(gg.x, px2, accx2[2 * q]);
                accx [2 * q + 1] = fma2(gg.y, px,  accx [2 * q + 1]);
                accx2[2 * q + 1] = fma2(gg.y, px2, accx2[2 * q + 1]);
            }
        }
    }

    // partials: chunk-major, coalesced STG.128
    ulonglong2* pg = reinterpret_cast<ulonglong2*>(g_P);
    #pragma unroll
    for (int p = 0; p < 16; p++) {
        int chunk = p * 8 + (tid >> 5);
        size_t idx = ((size_t)chunk * CTAS + bid) * 32 + (tid & 31);
        ulonglong2 v; v.x = accx[p]; v.y = accx2[p];
        pg[idx] = v;
    }
}

// ================= K3: reduce + finalize =================
__global__ void __launch_bounds__(256) k3_fin(const float* __restrict__ w,
                                              const float* __restrict__ b,
                                              float* __restrict__ out) {
    __shared__ __align__(16) float4 s_red4[8 * 32];
    __shared__ float s_S0v[2];

    const int tid  = threadIdx.x;
    const int wrp  = tid >> 5;
    const int lane = tid & 31;
    const int cb   = blockIdx.x;

    const float4* src = g_P + (size_t)cb * CTAS * 32;
    const int q4 = tid & 31;
    const int rg = tid >> 5;   // 8 row-groups over 128 source blocks
    float4 a = make_float4(0.f, 0.f, 0.f, 0.f);
    #pragma unroll
    for (int r = rg; r < CTAS; r += 8) {
        float4 v = src[r * 32 + q4];
        a.x += v.x; a.y += v.y; a.z += v.z; a.w += v.w;
    }
    s_red4[rg * 32 + q4] = a;

    if (wrp == 1) {   // S0 for this chunk's two k's
        int ks = lane >> 4;
        int j  = lane & 15;
        int p  = cb >> 3;
        float s = 0.0f;
        #pragma unroll
        for (int bb = j; bb < CTAS; bb += 16) s += g_PS0[bb * KK + 2 * p + ks];
        #pragma unroll
        for (int o = 1; o < 16; o <<= 1) s += __shfl_xor_sync(0xffffffffu, s, o);
        if (j == 0) s_S0v[ks] = s;
    }
    __syncthreads();

    if (tid < 32) {
        float4 tot = make_float4(0.f, 0.f, 0.f, 0.f);
        #pragma unroll
        for (int gq = 0; gq < 8; gq++) {
            float4 v = s_red4[gq * 32 + tid];
            tot.x += v.x; tot.y += v.y; tot.z += v.z; tot.w += v.w;
        }
        const int p  = cb >> 3;
        const int d  = (cb & 7) * 32 + tid;
        const int k0 = 2 * p, k1 = 2 * p + 1;
        const float invN   = 1.0f / (float)NROWS;
        const float invNs2 = invN * 0.70710678118654752440f;

        {
            float wv = w[k0 * DD + d], bv = b[k0 * DD + d], S0 = s_S0v[0];
            float mu  = wv * (tot.x + bv * S0) * invN;
            float Ey2 = wv * wv * (tot.z + 2.0f * bv * tot.x + bv * bv * S0);
            out[k0 * DD + d]           = (Ey2 - S0) * invNs2;
            out[KK * DD + k0 * DD + d] = mu;
        }
        {
            float wv = w[k1 * DD + d], bv = b[k1 * DD + d], S0 = s_S0v[1];
            float mu  = wv * (tot.y + bv * S0) * invN;
            float Ey2 = wv * wv * (tot.w + 2.0f * bv * tot.y + bv * bv * S0);
            out[k1 * DD + d]           = (Ey2 - S0) * invNs2;
            out[KK * DD + k1 * DD + d] = mu;
        }
    }
}

extern "C" void kernel_launch(void* const* d_in, const int* in_sizes, int n_in,
                              void* d_out, int out_size) {
    const float* x = (const float*)d_in[0];
    const float* w = (const float*)d_in[1];
    const float* b = (const float*)d_in[2];
    float* out = (float*)d_out;
    (void)in_sizes; (void)n_in; (void)out_size;

    cudaFuncSetAttribute(k1_gamma, cudaFuncAttributeMaxDynamicSharedMemorySize, SMEM1);
    k1_gamma<<<CTAS, 256, SMEM1>>>(x, w, b);
    k2_accum<<<CTAS, 256>>>(x);
    k3_fin<<<CTAS, 256>>>(w, b, out);
}

// round 15
// speedup vs baseline: 1.3435x; 1.2533x over previous
#include <cuda_runtime.h>
#include <cstdint>

// FisherLayer: N=8192, D=256, K=32 — two-pass, K1 on warp-level mma.sync (bf16).
//  K1: y4raw[n,k] = sum_d a*x^2 + u*x  (a=w^2, u=2w^2b), split-bf16 GEMM via
//      mma.sync.m16n8k16; gamma = softmax_k(-0.5*(y4raw + c_k)), c_k fp32.
//  K2: Sx[k,d]=sum_n g*x, Sx2[k,d]=sum_n g*x^2 (+S0) per-block partials.
//  K3: reduce; out_mu = w*(Sx+b*S0)/N;
//      out_sigma = (w^2*(Sx2+2b*Sx+b^2*S0)-S0)/(sqrt(2)N)

#define NROWS 8192
#define DD    256
#define KK    32
#define CTAS  128
#define RPC   64
#define ROWS1 64

typedef unsigned long long u64;
typedef unsigned int u32;

__device__ float g_G[NROWS * KK];
__device__ __align__(128) float4 g_P[128 * CTAS * 32];
__device__ float g_PS0[CTAS * KK];

__device__ __forceinline__ u64 pack2(float lo, float hi) {
    u64 r; asm("mov.b64 %0, {%1, %2};" : "=l"(r) : "f"(lo), "f"(hi)); return r;
}
__device__ __forceinline__ u64 fma2(u64 a, u64 b, u64 c) {
    u64 d; asm("fma.rn.f32x2 %0, %1, %2, %3;" : "=l"(d) : "l"(a), "l"(b), "l"(c)); return d;
}
__device__ __forceinline__ u32 bfp(float hi, float lo) {   // hi -> upper 16 bits
    u32 r; asm("cvt.rn.bf16x2.f32 %0, %1, %2;" : "=r"(r) : "f"(hi), "f"(lo)); return r;
}
__device__ __forceinline__ float blo(u32 v) { return __uint_as_float(v << 16); }
__device__ __forceinline__ float bhi(u32 v) { return __uint_as_float(v & 0xffff0000u); }

#define MMA(dd, a0, a1, a2, a3, b0, b1)                                        \
    asm volatile(                                                              \
        "mma.sync.aligned.m16n8k16.row.col.f32.bf16.bf16.f32 "                 \
        "{%0,%1,%2,%3}, {%4,%5,%6,%7}, {%8,%9}, {%0,%1,%2,%3};"                \
        : "+f"(dd[0]), "+f"(dd[1]), "+f"(dd[2]), "+f"(dd[3])                   \
        : "r"(a0), "r"(a1), "r"(a2), "r"(a3), "r"(b0), "r"(b1))

// ---------------- K1 ----------------
// dyn smem: B tables 4 variants x [32 n][264 bf16 row (528B, padded)] = 67584
//           s_y 64 x 33 fp32 = 8448; s_cp 256 f32; s_c 32 f32
#define PITCHB   528
#define BVSZ     16896           // 32 * 528
#define OFF_B    0
#define OFF_Y    67584
#define OFF_CP   76032
#define OFF_C    77056
#define SMEM1    77200

__global__ void __launch_bounds__(256, 1) k1_gamma_mma(const float* __restrict__ x,
                                                       const float* __restrict__ w,
                                                       const float* __restrict__ b) {
    extern __shared__ __align__(16) char smem[];
    float* s_y  = reinterpret_cast<float*>(smem + OFF_Y);
    float* s_cp = reinterpret_cast<float*>(smem + OFF_CP);
    float* s_c  = reinterpret_cast<float*>(smem + OFF_C);

    const int tid  = threadIdx.x;
    const int wid  = tid >> 5;
    const int lane = tid & 31;
    const int bid  = blockIdx.x;
    const int row0 = bid * ROWS1;

    // ---- build B tables (ah/al/uh/ul) + c_k partials ----
    {
        const int n  = tid >> 3;           // 0..31
        const int k0 = (tid & 7) * 32;     // 32 d-values per thread
        const float2* wp = reinterpret_cast<const float2*>(w + (size_t)n * DD + k0);
        const float2* bp = reinterpret_cast<const float2*>(b + (size_t)n * DD + k0);
        char* Bah = smem + OFF_B + 0 * BVSZ + n * PITCHB;
        char* Bal = smem + OFF_B + 1 * BVSZ + n * PITCHB;
        char* Buh = smem + OFF_B + 2 * BVSZ + n * PITCHB;
        char* Bul = smem + OFF_B + 3 * BVSZ + n * PITCHB;
        float cp = 0.0f;
        #pragma unroll
        for (int j = 0; j < 16; j++) {
            float2 wv = wp[j], bv = bp[j];
            float a0 = wv.x * wv.x, a1 = wv.y * wv.y;
            float u0 = 2.0f * a0 * bv.x, u1 = 2.0f * a1 * bv.y;
            cp += a0 * bv.x * bv.x + a1 * bv.y * bv.y;
            u32 ah = bfp(a1, a0);
            u32 al = bfp(a1 - bhi(ah), a0 - blo(ah));
            u32 uh = bfp(u1, u0);
            u32 ul = bfp(u1 - bhi(uh), u0 - blo(uh));
            const int off = (k0 + 2 * j) * 2;
            *reinterpret_cast<u32*>(Bah + off) = ah;
            *reinterpret_cast<u32*>(Bal + off) = al;
            *reinterpret_cast<u32*>(Buh + off) = uh;
            *reinterpret_cast<u32*>(Bul + off) = ul;
        }
        s_cp[tid] = cp;
    }
    __syncthreads();
    if (tid < 32) {
        float s = 0.0f;
        #pragma unroll
        for (int j = 0; j < 8; j++) s += s_cp[tid * 8 + j];
        s_c[tid] = s;
    }

    // ---- MMA mainloop: warp = (row-tile rt 16 rows, k-half kh 16 comps) ----
    const int rt = wid & 3;
    const int kh = wid >> 2;
    const int qr = lane >> 2;          // 0..7
    const int cb = (lane & 3) * 2;     // col base within 16-d kstep

    float d0[4] = {0.f, 0.f, 0.f, 0.f};   // ntile 0 (comps kh*16 + 0..7)
    float d1[4] = {0.f, 0.f, 0.f, 0.f};   // ntile 1 (comps kh*16 + 8..15)

    const float* xr1 = x + (size_t)(row0 + rt * 16 + qr) * DD;
    const float* xr2 = xr1 + 8 * DD;
    const char* Br0 = smem + OFF_B + (kh * 16 + qr) * PITCHB;       // ntile0 row
    const char* Br1 = Br0 + 8 * PITCHB;                              // ntile1 row

    #pragma unroll
    for (int kst = 0; kst < 16; kst++) {
        const int c1 = kst * 16 + cb;
        float2 v00 = *reinterpret_cast<const float2*>(xr1 + c1);
        float2 v01 = *reinterpret_cast<const float2*>(xr1 + c1 + 8);
        float2 v10 = *reinterpret_cast<const float2*>(xr2 + c1);
        float2 v11 = *reinterpret_cast<const float2*>(xr2 + c1 + 8);

        // xh / xl fragments
        u32 xh0 = bfp(v00.y, v00.x), xh1 = bfp(v10.y, v10.x);
        u32 xh2 = bfp(v01.y, v01.x), xh3 = bfp(v11.y, v11.x);
        u32 xl0 = bfp(v00.y - bhi(xh0), v00.x - blo(xh0));
        u32 xl1 = bfp(v10.y - bhi(xh1), v10.x - blo(xh1));
        u32 xl2 = bfp(v01.y - bhi(xh2), v01.x - blo(xh2));
        u32 xl3 = bfp(v11.y - bhi(xh3), v11.x - blo(xh3));

        // x^2 hi / lo fragments
        float q00x = v00.x * v00.x, q00y = v00.y * v00.y;
        float q10x = v10.x * v10.x, q10y = v10.y * v10.y;
        float q01x = v01.x * v01.x, q01y = v01.y * v01.y;
        float q11x = v11.x * v11.x, q11y = v11.y * v11.y;
        u32 qh0 = bfp(q00y, q00x), qh1 = bfp(q10y, q10x);
        u32 qh2 = bfp(q01y, q01x), qh3 = bfp(q11y, q11x);
        u32 ql0 = bfp(q00y - bhi(qh0), q00x - blo(qh0));
        u32 ql1 = bfp(q10y - bhi(qh1), q10x - blo(qh1));
        u32 ql2 = bfp(q01y - bhi(qh2), q01x - blo(qh2));
        u32 ql3 = bfp(q11y - bhi(qh3), q11x - blo(qh3));

        const int ko = (kst * 16 + cb) * 2;   // byte offset of b0 pair in row
        // ntile 0 B frags
        u32 ah0 = *reinterpret_cast<const u32*>(Br0 + ko);
        u32 ah1 = *reinterpret_cast<const u32*>(Br0 + ko + 16);
        u32 al0 = *reinterpret_cast<const u32*>(Br0 + BVSZ + ko);
        u32 al1 = *reinterpret_cast<const u32*>(Br0 + BVSZ + ko + 16);
        u32 uh0 = *reinterpret_cast<const u32*>(Br0 + 2 * BVSZ + ko);
        u32 uh1 = *reinterpret_cast<const u32*>(Br0 + 2 * BVSZ + ko + 16);
        u32 ul0 = *reinterpret_cast<const u32*>(Br0 + 3 * BVSZ + ko);
        u32 ul1 = *reinterpret_cast<const u32*>(Br0 + 3 * BVSZ + ko + 16);
        MMA(d0, qh0, qh1, qh2, qh3, ah0, ah1);
        MMA(d0, ql0, ql1, ql2, ql3, ah0, ah1);
        MMA(d0, qh0, qh1, qh2, qh3, al0, al1);
        MMA(d0, ql0, ql1, ql2, ql3, al0, al1);
        MMA(d0, xh0, xh1, xh2, xh3, uh0, uh1);
        MMA(d0, xl0, xl1, xl2, xl3, uh0, uh1);
        MMA(d0, xh0, xh1, xh2, xh3, ul0, ul1);
        MMA(d0, xl0, xl1, xl2, xl3, ul0, ul1);
        // ntile 1 B frags
        ah0 = *reinterpret_cast<const u32*>(Br1 + ko);
        ah1 = *reinterpret_cast<const u32*>(Br1 + ko + 16);
        al0 = *reinterpret_cast<const u32*>(Br1 + BVSZ + ko);
        al1 = *reinterpret_cast<const u32*>(Br1 + BVSZ + ko + 16);
        uh0 = *reinterpret_cast<const u32*>(Br1 + 2 * BVSZ + ko);
        uh1 = *reinterpret_cast<const u32*>(Br1 + 2 * BVSZ + ko + 16);
        ul0 = *reinterpret_cast<const u32*>(Br1 + 3 * BVSZ + ko);
        ul1 = *reinterpret_cast<const u32*>(Br1 + 3 * BVSZ + ko + 16);
        MMA(d1, qh0, qh1, qh2, qh3, ah0, ah1);
        MMA(d1, ql0, ql1, ql2, ql3, ah0, ah1);
        MMA(d1, qh0, qh1, qh2, qh3, al0, al1);
        MMA(d1, ql0, ql1, ql2, ql3, al0, al1);
        MMA(d1, xh0, xh1, xh2, xh3, uh0, uh1);
        MMA(d1, xl0, xl1, xl2, xl3, uh0, uh1);
        MMA(d1, xh0, xh1, xh2, xh3, ul0, ul1);
        MMA(d1, xl0, xl1, xl2, xl3, ul0, ul1);
    }

    // ---- write D fragments to padded smem ----
    {
        const int lr1 = rt * 16 + qr;
        const int lr2 = lr1 + 8;
        const int c0  = kh * 16 + cb;         // ntile0 cols
        s_y[lr1 * 33 + c0]     = d0[0];
        s_y[lr1 * 33 + c0 + 1] = d0[1];
        s_y[lr2 * 33 + c0]     = d0[2];
        s_y[lr2 * 33 + c0 + 1] = d0[3];
        s_y[lr1 * 33 + c0 + 8]     = d1[0];
        s_y[lr1 * 33 + c0 + 9]     = d1[1];
        s_y[lr2 * 33 + c0 + 8]     = d1[2];
        s_y[lr2 * 33 + c0 + 9]     = d1[3];
    }
    __syncthreads();

    // ---- softmax: warp wid owns rows wid*8..+8, lane = k ----
    #pragma unroll
    for (int i = 0; i < 8; i++) {
        const int row = wid * 8 + i;
        float y = -0.5f * (s_y[row * 33 + lane] + s_c[lane]);
        float m = y;
        #pragma unroll
        for (int o = 16; o; o >>= 1) m = fmaxf(m, __shfl_xor_sync(0xffffffffu, m, o));
        float e = __expf(y - m);
        float s = e;
        #pragma unroll
        for (int o = 16; o; o >>= 1) s += __shfl_xor_sync(0xffffffffu, s, o);
        g_G[(size_t)(row0 + row) * KK + lane] = e / s;
    }
}

// ---------------- K2: weighted accumulation (+S0) ----------------
__global__ void __launch_bounds__(256, 1) k2_accum(const float* __restrict__ x) {
    __shared__ __align__(16) float s_g[RPC * KK];
    __shared__ float s_red0[8 * 32];

    const int tid = threadIdx.x;
    const int bid = blockIdx.x;
    const int base_row = bid * RPC;

    {
        const float4* gg = reinterpret_cast<const float4*>(g_G + (size_t)base_row * KK);
        float4* sg4 = reinterpret_cast<float4*>(s_g);
        sg4[tid] = gg[tid];
        sg4[tid + 256] = gg[tid + 256];
    }
    __syncthreads();

    {
        int k0 = tid & 31, grp = tid >> 5;
        float s0p = 0.0f;
        #pragma unroll
        for (int r = grp; r < RPC; r += 8) s0p += s_g[r * KK + k0];
        s_red0[grp * 32 + k0] = s0p;
    }
    __syncthreads();
    if (tid < 32) {
        float s = 0.0f;
        #pragma unroll
        for (int j = 0; j < 8; j++) s += s_red0[j * 32 + tid];
        g_PS0[bid * KK + tid] = s;
    }

    u64 accx[16], accx2[16];
    #pragma unroll
    for (int p = 0; p < 16; p++) { accx[p] = 0ull; accx2[p] = 0ull; }

    const float* xb = x + (size_t)base_row * DD + tid;

    #pragma unroll 1
    for (int r0 = 0; r0 < RPC; r0 += 4) {
        float xv[4];
        #pragma unroll
        for (int i = 0; i < 4; i++) xv[i] = xb[(r0 + i) * DD];
        #pragma unroll
        for (int i = 0; i < 4; i++) {
            float v = xv[i];
            u64 px = pack2(v, v);
            float sq = v * v;
            u64 px2 = pack2(sq, sq);
            const ulonglong2* grow =
                reinterpret_cast<const ulonglong2*>(s_g + (r0 + i) * KK);
            #pragma unroll
            for (int q = 0; q < 8; q++) {
                ulonglong2 gg = grow[q];
                accx [2 * q]     = fma2(gg.x, px,  accx [2 * q]);
                accx2[2 * q]     = fma2(gg.x, px2, accx2[2 * q]);
                accx [2 * q + 1] = fma2(gg.y, px,  accx [2 * q + 1]);
                accx2[2 * q + 1] = fma2(gg.y, px2, accx2[2 * q + 1]);
            }
        }
    }

    ulonglong2* pg = reinterpret_cast<ulonglong2*>(g_P);
    #pragma unroll
    for (int p = 0; p < 16; p++) {
        int chunk = p * 8 + (tid >> 5);
        size_t idx = ((size_t)chunk * CTAS + bid) * 32 + (tid & 31);
        ulonglong2 v; v.x = accx[p]; v.y = accx2[p];
        pg[idx] = v;
    }
}

// ---------------- K3: reduce + finalize ----------------
__global__ void __launch_bounds__(256) k3_fin(const float* __restrict__ w,
                                              const float* __restrict__ b,
                                              float* __restrict__ out) {
    __shared__ __align__(16) float4 s_red4[8 * 32];
    __shared__ float s_S0v[2];

    const int tid  = threadIdx.x;
    const int wrp  = tid >> 5;
    const int lane = tid & 31;
    const int cb   = blockIdx.x;

    const float4* src = g_P + (size_t)cb * CTAS * 32;
    const int q4 = tid & 31;
    const int rg = tid >> 5;
    float4 a = make_float4(0.f, 0.f, 0.f, 0.f);
    #pragma unroll
    for (int r = rg; r < CTAS; r += 8) {
        float4 v = src[r * 32 + q4];
        a.x += v.x; a.y += v.y; a.z += v.z; a.w += v.w;
    }
    s_red4[rg * 32 + q4] = a;

    if (wrp == 1) {
        int ks = lane >> 4;
        int j  = lane & 15;
        int p  = cb >> 3;
        float s = 0.0f;
        #pragma unroll
        for (int bb = j; bb < CTAS; bb += 16) s += g_PS0[bb * KK + 2 * p + ks];
        #pragma unroll
        for (int o = 1; o < 16; o <<= 1) s += __shfl_xor_sync(0xffffffffu, s, o);
        if (j == 0) s_S0v[ks] = s;
    }
    __syncthreads();

    if (tid < 32) {
        float4 tot = make_float4(0.f, 0.f, 0.f, 0.f);
        #pragma unroll
        for (int gq = 0; gq < 8; gq++) {
            float4 v = s_red4[gq * 32 + tid];
            tot.x += v.x; tot.y += v.y; tot.z += v.z; tot.w += v.w;
        }
        const int p  = cb >> 3;
        const int d  = (cb & 7) * 32 + tid;
        const int k0 = 2 * p, k1 = 2 * p + 1;
        const float invN   = 1.0f / (float)NROWS;
        const float invNs2 = invN * 0.70710678118654752440f;

        {
            float wv = w[k0 * DD + d], bv = b[k0 * DD + d], S0 = s_S0v[0];
            float mu  = wv * (tot.x + bv * S0) * invN;
            float Ey2 = wv * wv * (tot.z + 2.0f * bv * tot.x + bv * bv * S0);
            out[k0 * DD + d]           = (Ey2 - S0) * invNs2;
            out[KK * DD + k0 * DD + d] = mu;
        }
        {
            float wv = w[k1 * DD + d], bv = b[k1 * DD + d], S0 = s_S0v[1];
            float mu  = wv * (tot.y + bv * S0) * invN;
            float Ey2 = wv * wv * (tot.w + 2.0f * bv * tot.y + bv * bv * S0);
            out[k1 * DD + d]           = (Ey2 - S0) * invNs2;
            out[KK * DD + k1 * DD + d] = mu;
        }
    }
}

extern "C" void kernel_launch(void* const* d_in, const int* in_sizes, int n_in,
                              void* d_out, int out_size) {
    const float* x = (const float*)d_in[0];
    const float* w = (const float*)d_in[1];
    const float* b = (const float*)d_in[2];
    float* out = (float*)d_out;
    (void)in_sizes; (void)n_in; (void)out_size;

    cudaFuncSetAttribute(k1_gamma_mma, cudaFuncAttributeMaxDynamicSharedMemorySize,
                         SMEM1);
    k1_gamma_mma<<<CTAS, 256, SMEM1>>>(x, w, b);
    k2_accum<<<CTAS, 256>>>(x);
    k3_fin<<<CTAS, 256>>>(w, b, out);
}